// round 1
// baseline (speedup 1.0000x reference)
#include <cuda_runtime.h>
#include <math.h>

#define B_DIM 4
#define S_DIM 4096
#define D_DIM 1024
#define M_TOK (B_DIM * S_DIM)   // 16384 tokens

// Scratch (allocation-free rule: __device__ globals)
__device__ float g_Q[(size_t)M_TOK * D_DIM];            //  64 MB
__device__ float g_K[(size_t)M_TOK * D_DIM];            //  64 MB
__device__ float g_V[(size_t)M_TOK * D_DIM];            //  64 MB
__device__ float g_S[(size_t)B_DIM * S_DIM * S_DIM];    // 256 MB

// ---------------------------------------------------------------------------
// NT GEMM: C[m,n] = scale * sum_k A[m,k] * B[n,k]  (+ bias[n])
// A row-major [M,K], B row-major [N,K]. 128x128 tile, BK=8, 8x8 per thread.
// ---------------------------------------------------------------------------
__global__ void __launch_bounds__(256) gemm_nt(
    const float* __restrict__ A, const float* __restrict__ B,
    float* __restrict__ C, const float* __restrict__ bias,
    int M, int N, int K, float scale,
    size_t sA, size_t sB, size_t sC)
{
    A += (size_t)blockIdx.z * sA;
    B += (size_t)blockIdx.z * sB;
    C += (size_t)blockIdx.z * sC;

    __shared__ float As[8][128];
    __shared__ float Bs[8][128];

    const int tid = threadIdx.x;
    const int m0 = blockIdx.y * 128;
    const int n0 = blockIdx.x * 128;
    const int lr = tid >> 1;           // 0..127: tile row to load
    const int lc = (tid & 1) << 2;     // 0 or 4: k-offset of float4
    const int ty = tid >> 4;           // 0..15
    const int tx = tid & 15;           // 0..15

    const float* Ap = A + (size_t)(m0 + lr) * K + lc;
    const float* Bp = B + (size_t)(n0 + lr) * K + lc;

    float acc[8][8];
#pragma unroll
    for (int i = 0; i < 8; i++)
#pragma unroll
        for (int j = 0; j < 8; j++) acc[i][j] = 0.f;

    for (int k0 = 0; k0 < K; k0 += 8) {
        float4 av = *(const float4*)(Ap + k0);
        float4 bv = *(const float4*)(Bp + k0);
        __syncthreads();
        As[lc + 0][lr] = av.x; As[lc + 1][lr] = av.y;
        As[lc + 2][lr] = av.z; As[lc + 3][lr] = av.w;
        Bs[lc + 0][lr] = bv.x; Bs[lc + 1][lr] = bv.y;
        Bs[lc + 2][lr] = bv.z; Bs[lc + 3][lr] = bv.w;
        __syncthreads();
#pragma unroll
        for (int kk = 0; kk < 8; kk++) {
            float4 a0 = *(const float4*)&As[kk][ty * 8];
            float4 a1 = *(const float4*)&As[kk][ty * 8 + 4];
            float4 b0 = *(const float4*)&Bs[kk][tx * 8];
            float4 b1 = *(const float4*)&Bs[kk][tx * 8 + 4];
            float a[8] = {a0.x, a0.y, a0.z, a0.w, a1.x, a1.y, a1.z, a1.w};
            float b[8] = {b0.x, b0.y, b0.z, b0.w, b1.x, b1.y, b1.z, b1.w};
#pragma unroll
            for (int i = 0; i < 8; i++)
#pragma unroll
                for (int j = 0; j < 8; j++)
                    acc[i][j] = fmaf(a[i], b[j], acc[i][j]);
        }
    }

    float bb[8];
#pragma unroll
    for (int j = 0; j < 8; j++)
        bb[j] = bias ? bias[n0 + tx * 8 + j] : 0.f;

#pragma unroll
    for (int i = 0; i < 8; i++) {
        float* Cp = C + (size_t)(m0 + ty * 8 + i) * N + n0 + tx * 8;
        float4 v0, v1;
        v0.x = acc[i][0] * scale + bb[0];
        v0.y = acc[i][1] * scale + bb[1];
        v0.z = acc[i][2] * scale + bb[2];
        v0.w = acc[i][3] * scale + bb[3];
        v1.x = acc[i][4] * scale + bb[4];
        v1.y = acc[i][5] * scale + bb[5];
        v1.z = acc[i][6] * scale + bb[6];
        v1.w = acc[i][7] * scale + bb[7];
        *(float4*)Cp = v0;
        *(float4*)(Cp + 4) = v1;
    }
}

// ---------------------------------------------------------------------------
// NN GEMM: C[m,n] = sum_k A[m,k] * B[k,n]
// A row-major [M,K], B row-major [K,N]. Same tiling as above.
// ---------------------------------------------------------------------------
__global__ void __launch_bounds__(256) gemm_nn(
    const float* __restrict__ A, const float* __restrict__ B,
    float* __restrict__ C,
    int M, int N, int K,
    size_t sA, size_t sB, size_t sC)
{
    A += (size_t)blockIdx.z * sA;
    B += (size_t)blockIdx.z * sB;
    C += (size_t)blockIdx.z * sC;

    __shared__ float As[8][128];
    __shared__ float Bs[8][128];

    const int tid = threadIdx.x;
    const int m0 = blockIdx.y * 128;
    const int n0 = blockIdx.x * 128;
    const int lr = tid >> 1;           // A-load row
    const int lc = (tid & 1) << 2;     // A-load k-offset
    const int br = tid >> 5;           // 0..7: B-load k row
    const int bc = (tid & 31) << 2;    // 0..124: B-load col
    const int ty = tid >> 4;
    const int tx = tid & 15;

    const float* Ap = A + (size_t)(m0 + lr) * K + lc;
    const float* Bp = B + (size_t)br * N + n0 + bc;

    float acc[8][8];
#pragma unroll
    for (int i = 0; i < 8; i++)
#pragma unroll
        for (int j = 0; j < 8; j++) acc[i][j] = 0.f;

    for (int k0 = 0; k0 < K; k0 += 8) {
        float4 av = *(const float4*)(Ap + k0);
        float4 bv = *(const float4*)(Bp + (size_t)k0 * N);
        __syncthreads();
        As[lc + 0][lr] = av.x; As[lc + 1][lr] = av.y;
        As[lc + 2][lr] = av.z; As[lc + 3][lr] = av.w;
        *(float4*)&Bs[br][bc] = bv;
        __syncthreads();
#pragma unroll
        for (int kk = 0; kk < 8; kk++) {
            float4 a0 = *(const float4*)&As[kk][ty * 8];
            float4 a1 = *(const float4*)&As[kk][ty * 8 + 4];
            float4 b0 = *(const float4*)&Bs[kk][tx * 8];
            float4 b1 = *(const float4*)&Bs[kk][tx * 8 + 4];
            float a[8] = {a0.x, a0.y, a0.z, a0.w, a1.x, a1.y, a1.z, a1.w};
            float b[8] = {b0.x, b0.y, b0.z, b0.w, b1.x, b1.y, b1.z, b1.w};
#pragma unroll
            for (int i = 0; i < 8; i++)
#pragma unroll
                for (int j = 0; j < 8; j++)
                    acc[i][j] = fmaf(a[i], b[j], acc[i][j]);
        }
    }

#pragma unroll
    for (int i = 0; i < 8; i++) {
        float* Cp = C + (size_t)(m0 + ty * 8 + i) * N + n0 + tx * 8;
        float4 v0, v1;
        v0.x = acc[i][0]; v0.y = acc[i][1]; v0.z = acc[i][2]; v0.w = acc[i][3];
        v1.x = acc[i][4]; v1.y = acc[i][5]; v1.z = acc[i][6]; v1.w = acc[i][7];
        *(float4*)Cp = v0;
        *(float4*)(Cp + 4) = v1;
    }
}

// ---------------------------------------------------------------------------
// Row softmax over S_DIM=4096 elements. One block (256 threads) per row.
// ---------------------------------------------------------------------------
__global__ void __launch_bounds__(256) softmax_kernel(float* __restrict__ P)
{
    float4* row = (float4*)(P + (size_t)blockIdx.x * S_DIM);
    const int tid = threadIdx.x;
    __shared__ float sh[32];

    float4 v[4];
    float mx = -INFINITY;
#pragma unroll
    for (int i = 0; i < 4; i++) {
        v[i] = row[tid + i * 256];
        mx = fmaxf(mx, fmaxf(fmaxf(v[i].x, v[i].y), fmaxf(v[i].z, v[i].w)));
    }
#pragma unroll
    for (int o = 16; o; o >>= 1) mx = fmaxf(mx, __shfl_xor_sync(0xffffffffu, mx, o));
    if ((tid & 31) == 0) sh[tid >> 5] = mx;
    __syncthreads();
    if (tid < 32) {
        float r = (tid < 8) ? sh[tid] : -INFINITY;
#pragma unroll
        for (int o = 4; o; o >>= 1) r = fmaxf(r, __shfl_xor_sync(0xffffffffu, r, o));
        if (tid == 0) sh[0] = r;
    }
    __syncthreads();
    mx = sh[0];
    __syncthreads();

    float sum = 0.f;
#pragma unroll
    for (int i = 0; i < 4; i++) {
        v[i].x = __expf(v[i].x - mx); sum += v[i].x;
        v[i].y = __expf(v[i].y - mx); sum += v[i].y;
        v[i].z = __expf(v[i].z - mx); sum += v[i].z;
        v[i].w = __expf(v[i].w - mx); sum += v[i].w;
    }
#pragma unroll
    for (int o = 16; o; o >>= 1) sum += __shfl_xor_sync(0xffffffffu, sum, o);
    if ((tid & 31) == 0) sh[tid >> 5] = sum;
    __syncthreads();
    if (tid < 32) {
        float r = (tid < 8) ? sh[tid] : 0.f;
#pragma unroll
        for (int o = 4; o; o >>= 1) r += __shfl_xor_sync(0xffffffffu, r, o);
        if (tid == 0) sh[0] = r;
    }
    __syncthreads();
    const float inv = 1.0f / sh[0];

#pragma unroll
    for (int i = 0; i < 4; i++) {
        v[i].x *= inv; v[i].y *= inv; v[i].z *= inv; v[i].w *= inv;
        row[tid + i * 256] = v[i];
    }
}

// ---------------------------------------------------------------------------
extern "C" void kernel_launch(void* const* d_in, const int* in_sizes, int n_in,
                              void* d_out, int out_size)
{
    (void)in_sizes; (void)n_in; (void)out_size;
    const float* x  = (const float*)d_in[0];
    const float* Wq = (const float*)d_in[1];
    const float* bq = (const float*)d_in[2];
    const float* Wk = (const float*)d_in[3];
    const float* bk = (const float*)d_in[4];
    const float* Wv = (const float*)d_in[5];
    const float* bv = (const float*)d_in[6];
    float* out = (float*)d_out;

    float *Q, *K, *V, *S;
    cudaGetSymbolAddress((void**)&Q, g_Q);
    cudaGetSymbolAddress((void**)&K, g_K);
    cudaGetSymbolAddress((void**)&V, g_V);
    cudaGetSymbolAddress((void**)&S, g_S);

    const dim3 blk(256);

    // QKV projections: C = x . W^T + b   (M=16384, N=1024, K=1024)
    const dim3 gProj(D_DIM / 128, M_TOK / 128, 1);
    gemm_nt<<<gProj, blk>>>(x, Wq, Q, bq, M_TOK, D_DIM, D_DIM, 1.f, 0, 0, 0);
    gemm_nt<<<gProj, blk>>>(x, Wk, K, bk, M_TOK, D_DIM, D_DIM, 1.f, 0, 0, 0);
    gemm_nt<<<gProj, blk>>>(x, Wv, V, bv, M_TOK, D_DIM, D_DIM, 1.f, 0, 0, 0);

    // scores = Q . K^T / 32   (per batch: M=N=4096, K=1024)
    const dim3 gScore(S_DIM / 128, S_DIM / 128, B_DIM);
    gemm_nt<<<gScore, blk>>>(Q, K, S, nullptr, S_DIM, S_DIM, D_DIM, 1.0f / 32.0f,
                             (size_t)S_DIM * D_DIM, (size_t)S_DIM * D_DIM,
                             (size_t)S_DIM * S_DIM);

    // softmax over last axis, one block per row
    softmax_kernel<<<B_DIM * S_DIM, blk>>>(S);

    // out = P . V   (per batch: M=4096, N=1024, K=4096)
    const dim3 gPV(D_DIM / 128, S_DIM / 128, B_DIM);
    gemm_nn<<<gPV, blk>>>(S, V, out, S_DIM, D_DIM, S_DIM,
                          (size_t)S_DIM * S_DIM, (size_t)S_DIM * D_DIM,
                          (size_t)S_DIM * D_DIM);
}

// round 3
// speedup vs baseline: 4.0589x; 4.0589x over previous
#include <cuda_runtime.h>
#include <stdint.h>
#include <math.h>

#define B_DIM 4
#define S_DIM 4096
#define D_DIM 1024
#define M_TOK (B_DIM * S_DIM)   // 16384

#define BM 128
#define BN 128
#define BK 32
#define LDA 36                              // padded row stride (floats)
#define STAGE_FLOATS (2 * 128 * LDA)        // A tile then B tile
#define STAGE_BYTES (STAGE_FLOATS * 4)      // 36864 B
#define STAGES 3
#define SMEM_BYTES (STAGES * STAGE_BYTES)   // 110592 B

// Scratch (__device__ globals per allocation-free rule)
__device__ float g_Q [(size_t)M_TOK * D_DIM];           // 64 MB
__device__ float g_K [(size_t)M_TOK * D_DIM];           // 64 MB
__device__ float g_Vt[(size_t)B_DIM * D_DIM * S_DIM];   // 64 MB, [b][d][s]
__device__ float g_S [(size_t)B_DIM * S_DIM * S_DIM];   // 256 MB

__device__ __forceinline__ uint32_t smem_u32(const void* p) {
    uint32_t a;
    asm("{ .reg .u64 t; cvta.to.shared.u64 t, %1; cvt.u32.u64 %0, t; }"
        : "=r"(a) : "l"(p));
    return a;
}

__device__ __forceinline__ uint32_t f2tf(float f) {
    uint32_t u;
    asm("cvt.rna.tf32.f32 %0, %1;" : "=r"(u) : "f"(f));
    return u;
}

__device__ __forceinline__ void cp16(uint32_t dst, const void* src) {
    asm volatile("cp.async.cg.shared.global [%0], [%1], 16;" :: "r"(dst), "l"(src));
}

// ---------------------------------------------------------------------------
// tf32 mma.sync NT GEMM: C[m,n] = sum_k A[m,k]*B[n,k] (+ bias[n])
// A: [M,K] row-major. B: [N,K] row-major.
// mode 0: C row-major [M, ldc].  mode 1: transposed store C[b][n][s] (g_Vt).
// ---------------------------------------------------------------------------
__global__ void __launch_bounds__(256, 2) gemm_mma(
    const float* __restrict__ A, const float* __restrict__ B,
    float* __restrict__ C, const float* __restrict__ bias,
    int K, int ldc, size_t sA, size_t sB, size_t sC, int mode)
{
    extern __shared__ float sm[];
    const uint32_t smbase = smem_u32(sm);

    A += (size_t)blockIdx.z * sA;
    B += (size_t)blockIdx.z * sB;
    C += (size_t)blockIdx.z * sC;

    const int tid  = threadIdx.x;
    const int wid  = tid >> 5;
    const int lane = tid & 31;
    const int wm = wid >> 2;          // 0..1  (M warp row)
    const int wn = wid & 3;           // 0..3  (N warp col)
    const int r  = lane >> 2;         // 0..7
    const int c  = lane & 3;          // 0..3
    const int m0 = blockIdx.y * BM;
    const int n0 = blockIdx.x * BN;

    // global load mapping: thread loads 4 float4s of A row (tid>>1) and B row (tid>>1)
    const int lrow = tid >> 1;                // 0..127
    const int lco  = (tid & 1) * 16;          // float offset within row
    const float* gA = A + (size_t)(m0 + lrow) * K + lco;
    const float* gB = B + (size_t)(n0 + lrow) * K + lco;
    const uint32_t dstA = lrow * (LDA * 4) + (tid & 1) * 64;  // bytes, within A tile
    const uint32_t dstB = dstA + 128 * LDA * 4;

    const int NC = K / BK;

    float acc[4][4][4];
#pragma unroll
    for (int i = 0; i < 4; i++)
#pragma unroll
        for (int j = 0; j < 4; j++)
#pragma unroll
            for (int v = 0; v < 4; v++) acc[i][j][v] = 0.f;

    auto load_chunk = [&](int ch) {
        if (ch < NC) {
            const uint32_t st = smbase + (uint32_t)(ch % STAGES) * STAGE_BYTES;
            const float* pa = gA + ch * BK;
            const float* pb = gB + ch * BK;
#pragma unroll
            for (int j = 0; j < 4; j++) {
                cp16(st + dstA + j * 16, pa + j * 4);
                cp16(st + dstB + j * 16, pb + j * 4);
            }
        }
        asm volatile("cp.async.commit_group;");
    };

    load_chunk(0);
    load_chunk(1);

    for (int i = 0; i < NC; i++) {
        asm volatile("cp.async.wait_group 1;");
        __syncthreads();
        load_chunk(i + 2);

        const float* As = sm + (i % STAGES) * STAGE_FLOATS;
        const float* Bs = As + 128 * LDA;
#pragma unroll
        for (int s = 0; s < 4; s++) {
            uint32_t ua[4][4], ub[4][2];
#pragma unroll
            for (int mf = 0; mf < 4; mf++) {
                const float* ap = As + (wm * 64 + mf * 16 + r) * LDA + 8 * s + c;
                ua[mf][0] = f2tf(ap[0]);
                ua[mf][1] = f2tf(ap[8 * LDA]);
                ua[mf][2] = f2tf(ap[4]);
                ua[mf][3] = f2tf(ap[8 * LDA + 4]);
            }
#pragma unroll
            for (int nf = 0; nf < 4; nf++) {
                const float* bp = Bs + (wn * 32 + nf * 8 + r) * LDA + 8 * s + c;
                ub[nf][0] = f2tf(bp[0]);
                ub[nf][1] = f2tf(bp[4]);
            }
#pragma unroll
            for (int mf = 0; mf < 4; mf++)
#pragma unroll
                for (int nf = 0; nf < 4; nf++) {
                    asm volatile(
                        "mma.sync.aligned.m16n8k8.row.col.f32.tf32.tf32.f32 "
                        "{%0,%1,%2,%3}, {%4,%5,%6,%7}, {%8,%9}, {%0,%1,%2,%3};"
                        : "+f"(acc[mf][nf][0]), "+f"(acc[mf][nf][1]),
                          "+f"(acc[mf][nf][2]), "+f"(acc[mf][nf][3])
                        : "r"(ua[mf][0]), "r"(ua[mf][1]), "r"(ua[mf][2]), "r"(ua[mf][3]),
                          "r"(ub[nf][0]), "r"(ub[nf][1]));
                }
        }
    }

    if (mode == 0) {
        // direct row-major epilogue
#pragma unroll
        for (int mf = 0; mf < 4; mf++) {
            const int row0 = m0 + wm * 64 + mf * 16 + r;
#pragma unroll
            for (int nf = 0; nf < 4; nf++) {
                const int col = n0 + wn * 32 + nf * 8 + 2 * c;
                float b0 = 0.f, b1 = 0.f;
                if (bias) { b0 = bias[col]; b1 = bias[col + 1]; }
                float2 v0 = { acc[mf][nf][0] + b0, acc[mf][nf][1] + b1 };
                float2 v1 = { acc[mf][nf][2] + b0, acc[mf][nf][3] + b1 };
                *(float2*)(C + (size_t)row0 * ldc + col) = v0;
                *(float2*)(C + (size_t)(row0 + 8) * ldc + col) = v1;
            }
        }
    } else {
        // transposed epilogue through smem: Ts[n][m], LDT=132 floats
        __syncthreads();                 // pipeline smem no longer needed
        float* Ts = sm;
#pragma unroll
        for (int mf = 0; mf < 4; mf++) {
            const int ml0 = wm * 64 + mf * 16 + r;
#pragma unroll
            for (int nf = 0; nf < 4; nf++) {
                const int nl = wn * 32 + nf * 8 + 2 * c;
                Ts[(nl    ) * 132 + ml0    ] = acc[mf][nf][0];
                Ts[(nl + 1) * 132 + ml0    ] = acc[mf][nf][1];
                Ts[(nl    ) * 132 + ml0 + 8] = acc[mf][nf][2];
                Ts[(nl + 1) * 132 + ml0 + 8] = acc[mf][nf][3];
            }
        }
        __syncthreads();
        const int bbatch = m0 >> 12;
        const int sbase  = m0 & (S_DIM - 1);
#pragma unroll
        for (int it = 0; it < 16; it++) {
            const int idx = tid + it * 256;        // 0..4095
            const int row = idx >> 5;              // n within tile
            const int f   = (idx & 31) * 4;        // m within tile
            float4 v = *(const float4*)(Ts + row * 132 + f);
            const float bv = bias[n0 + row];
            v.x += bv; v.y += bv; v.z += bv; v.w += bv;
            *(float4*)(C + ((size_t)bbatch * D_DIM + n0 + row) * S_DIM + sbase + f) = v;
        }
    }
}

// ---------------------------------------------------------------------------
// Row softmax over S_DIM with folded 1/32 scale: softmax(scale * row).
// ---------------------------------------------------------------------------
__global__ void __launch_bounds__(256) softmax_kernel(float* __restrict__ P, float scale)
{
    float4* row = (float4*)(P + (size_t)blockIdx.x * S_DIM);
    const int tid = threadIdx.x;
    __shared__ float sh[32];

    float4 v[4];
    float mx = -INFINITY;
#pragma unroll
    for (int i = 0; i < 4; i++) {
        v[i] = row[tid + i * 256];
        mx = fmaxf(mx, fmaxf(fmaxf(v[i].x, v[i].y), fmaxf(v[i].z, v[i].w)));
    }
#pragma unroll
    for (int o = 16; o; o >>= 1) mx = fmaxf(mx, __shfl_xor_sync(0xffffffffu, mx, o));
    if ((tid & 31) == 0) sh[tid >> 5] = mx;
    __syncthreads();
    if (tid < 32) {
        float t = (tid < 8) ? sh[tid] : -INFINITY;
#pragma unroll
        for (int o = 4; o; o >>= 1) t = fmaxf(t, __shfl_xor_sync(0xffffffffu, t, o));
        if (tid == 0) sh[0] = t;
    }
    __syncthreads();
    mx = sh[0];
    __syncthreads();

    float sum = 0.f;
#pragma unroll
    for (int i = 0; i < 4; i++) {
        v[i].x = __expf((v[i].x - mx) * scale); sum += v[i].x;
        v[i].y = __expf((v[i].y - mx) * scale); sum += v[i].y;
        v[i].z = __expf((v[i].z - mx) * scale); sum += v[i].z;
        v[i].w = __expf((v[i].w - mx) * scale); sum += v[i].w;
    }
#pragma unroll
    for (int o = 16; o; o >>= 1) sum += __shfl_xor_sync(0xffffffffu, sum, o);
    if ((tid & 31) == 0) sh[tid >> 5] = sum;
    __syncthreads();
    if (tid < 32) {
        float t = (tid < 8) ? sh[tid] : 0.f;
#pragma unroll
        for (int o = 4; o; o >>= 1) t += __shfl_xor_sync(0xffffffffu, t, o);
        if (tid == 0) sh[0] = t;
    }
    __syncthreads();
    const float inv = 1.0f / sh[0];

#pragma unroll
    for (int i = 0; i < 4; i++) {
        v[i].x *= inv; v[i].y *= inv; v[i].z *= inv; v[i].w *= inv;
        row[tid + i * 256] = v[i];
    }
}

// ---------------------------------------------------------------------------
extern "C" void kernel_launch(void* const* d_in, const int* in_sizes, int n_in,
                              void* d_out, int out_size)
{
    (void)in_sizes; (void)n_in; (void)out_size;
    const float* x  = (const float*)d_in[0];
    const float* Wq = (const float*)d_in[1];
    const float* bq = (const float*)d_in[2];
    const float* Wk = (const float*)d_in[3];
    const float* bk = (const float*)d_in[4];
    const float* Wv = (const float*)d_in[5];
    const float* bv = (const float*)d_in[6];
    float* out = (float*)d_out;

    float *Q, *K, *Vt, *S;
    cudaGetSymbolAddress((void**)&Q,  g_Q);
    cudaGetSymbolAddress((void**)&K,  g_K);
    cudaGetSymbolAddress((void**)&Vt, g_Vt);
    cudaGetSymbolAddress((void**)&S,  g_S);

    cudaFuncSetAttribute(gemm_mma, cudaFuncAttributeMaxDynamicSharedMemorySize, SMEM_BYTES);

    const dim3 blk(256);

    // QKV projections (M=16384, N=1024, K=1024)
    const dim3 gProj(D_DIM / BN, M_TOK / BM, 1);
    gemm_mma<<<gProj, blk, SMEM_BYTES>>>(x, Wq, Q,  bq, D_DIM, D_DIM, 0, 0, 0, 0);
    gemm_mma<<<gProj, blk, SMEM_BYTES>>>(x, Wk, K,  bk, D_DIM, D_DIM, 0, 0, 0, 0);
    gemm_mma<<<gProj, blk, SMEM_BYTES>>>(x, Wv, Vt, bv, D_DIM, 0,     0, 0, 0, 1);

    // scores = Q . K^T (1/32 folded into softmax)
    const dim3 gScore(S_DIM / BN, S_DIM / BM, B_DIM);
    gemm_mma<<<gScore, blk, SMEM_BYTES>>>(Q, K, S, nullptr, D_DIM, S_DIM,
                                          (size_t)S_DIM * D_DIM,
                                          (size_t)S_DIM * D_DIM,
                                          (size_t)S_DIM * S_DIM, 0);

    softmax_kernel<<<B_DIM * S_DIM, 256>>>(S, 1.0f / 32.0f);

    // out = P . Vt^T (NT: Vt rows are d, ldb = S_DIM)
    const dim3 gPV(D_DIM / BN, S_DIM / BM, B_DIM);
    gemm_mma<<<gPV, blk, SMEM_BYTES>>>(S, Vt, out, nullptr, S_DIM, D_DIM,
                                       (size_t)S_DIM * S_DIM,
                                       (size_t)D_DIM * S_DIM,
                                       (size_t)S_DIM * D_DIM, 0);
}

// round 6
// speedup vs baseline: 4.3890x; 1.0813x over previous
#include <cuda_runtime.h>
#include <stdint.h>
#include <math.h>

#define B_DIM 4
#define S_DIM 4096
#define D_DIM 1024
#define M_TOK (B_DIM * S_DIM)   // 16384

#define BM 128
#define BN 128
#define BK 32                                // floats; 8 chunks of 16B per row
#define A_TILE_FLOATS (128 * 32)             // 4096
#define STAGE_FLOATS (2 * A_TILE_FLOATS)     // 8192 (A then B)
#define STAGE_BYTES (STAGE_FLOATS * 4)       // 32768
#define STAGES 4
#define SMEM_BYTES (STAGES * STAGE_BYTES)    // 131072

// Scratch (__device__ globals per allocation-free rule)
__device__ float g_Q [(size_t)M_TOK * D_DIM];           // 64 MB
__device__ float g_K [(size_t)M_TOK * D_DIM];           // 64 MB
__device__ float g_Vt[(size_t)B_DIM * D_DIM * S_DIM];   // 64 MB, [b][d][s]
__device__ float g_S [(size_t)B_DIM * S_DIM * S_DIM];   // 256 MB

__device__ __forceinline__ uint32_t smem_u32(const void* p) {
    uint32_t a;
    asm("{ .reg .u64 t; cvta.to.shared.u64 t, %1; cvt.u32.u64 %0, t; }"
        : "=r"(a) : "l"(p));
    return a;
}

__device__ __forceinline__ uint32_t f2tf(float f) {
    uint32_t u;
    asm("cvt.rna.tf32.f32 %0, %1;" : "=r"(u) : "f"(f));
    return u;
}

__device__ __forceinline__ void cp16(uint32_t dst, const void* src) {
    asm volatile("cp.async.cg.shared.global [%0], [%1], 16;" :: "r"(dst), "l"(src));
}

// ---------------------------------------------------------------------------
// tf32 mma.sync NT GEMM: C[m,n] = sum_k A[m,k]*B[n,k] (+ bias[n])
// A: [M,K] row-major. B: [N,K] row-major.
// Smem layout: 128-byte rows (32 floats), 16B chunk ch stored at ch^(row&7).
// mode 0: C row-major [M, ldc].  mode 1: transposed store C[b][n][s] (g_Vt).
// ---------------------------------------------------------------------------
__global__ void __launch_bounds__(256, 1) gemm_mma(
    const float* __restrict__ A, const float* __restrict__ B,
    float* __restrict__ C, const float* __restrict__ bias,
    int K, int ldc, size_t sA, size_t sB, size_t sC, int mode)
{
    extern __shared__ float sm[];
    const uint32_t smbase = smem_u32(sm);

    A += (size_t)blockIdx.z * sA;
    B += (size_t)blockIdx.z * sB;
    C += (size_t)blockIdx.z * sC;

    const int tid  = threadIdx.x;
    const int wid  = tid >> 5;
    const int lane = tid & 31;
    const int wm = wid >> 2;          // 0..1  (M warp row)
    const int wn = wid & 3;           // 0..3  (N warp col)
    const int r  = lane >> 2;         // 0..7
    const int c  = lane & 3;          // 0..3
    const int m0 = blockIdx.y * BM;
    const int n0 = blockIdx.x * BN;

    // ---- global -> smem mapping (swizzled) ----
    const int lrow = tid >> 1;                 // 0..127
    const int o4   = (tid & 1) * 4;            // starting 16B chunk (0 or 4)
    const int xr   = lrow & 7;
    const float* gA = A + (size_t)(m0 + lrow) * K + o4 * 4;
    const float* gB = B + (size_t)(n0 + lrow) * K + o4 * 4;
    uint32_t dstA[4], dstB[4];
#pragma unroll
    for (int j = 0; j < 4; j++) {
        dstA[j] = (uint32_t)lrow * 128 + (uint32_t)(((o4 + j) ^ xr) << 4);
        dstB[j] = dstA[j] + A_TILE_FLOATS * 4;
    }

    // ---- fragment base offsets (floats, within tile; +c folded into koff) ----
    int aoff[4], boff[4];
#pragma unroll
    for (int mf = 0; mf < 4; mf++) aoff[mf] = (wm * 64 + mf * 16 + r) * 32;
#pragma unroll
    for (int nf = 0; nf < 4; nf++) boff[nf] = (wn * 32 + nf * 8 + r) * 32;

    const int NC = K / BK;

    float acc[4][4][4];
#pragma unroll
    for (int i = 0; i < 4; i++)
#pragma unroll
        for (int j = 0; j < 4; j++)
#pragma unroll
            for (int v = 0; v < 4; v++) acc[i][j][v] = 0.f;

    auto load_chunk = [&](int ch) {
        if (ch < NC) {
            const uint32_t st = smbase + (uint32_t)(ch & (STAGES - 1)) * STAGE_BYTES;
            const float* pa = gA + ch * BK;
            const float* pb = gB + ch * BK;
#pragma unroll
            for (int j = 0; j < 4; j++) {
                cp16(st + dstA[j], pa + j * 4);
                cp16(st + dstB[j], pb + j * 4);
            }
        }
        asm volatile("cp.async.commit_group;");
    };

    load_chunk(0);
    load_chunk(1);
    load_chunk(2);

    for (int i = 0; i < NC; i++) {
        asm volatile("cp.async.wait_group 2;");
        __syncthreads();
        load_chunk(i + 3);

        const float* As = sm + (i & (STAGES - 1)) * STAGE_FLOATS;
        const float* Bs = As + A_TILE_FLOATS;

        uint32_t ua[2][4][4], ub[2][4][2];

        auto frag_ld = [&](int s, uint32_t (&fa)[4][4], uint32_t (&fb)[4][2]) {
            const int koff = (((2 * s) ^ r) << 2) + c;
            const int koff2 = koff ^ 4;
#pragma unroll
            for (int mf = 0; mf < 4; mf++) {
                fa[mf][0] = f2tf(As[aoff[mf] + koff]);
                fa[mf][1] = f2tf(As[aoff[mf] + 256 + koff]);
                fa[mf][2] = f2tf(As[aoff[mf] + koff2]);
                fa[mf][3] = f2tf(As[aoff[mf] + 256 + koff2]);
            }
#pragma unroll
            for (int nf = 0; nf < 4; nf++) {
                fb[nf][0] = f2tf(Bs[boff[nf] + koff]);
                fb[nf][1] = f2tf(Bs[boff[nf] + koff2]);
            }
        };

        frag_ld(0, ua[0], ub[0]);
#pragma unroll
        for (int s = 0; s < 4; s++) {
            if (s < 3) frag_ld(s + 1, ua[(s + 1) & 1], ub[(s + 1) & 1]);
            const int cur = s & 1;
#pragma unroll
            for (int mf = 0; mf < 4; mf++)
#pragma unroll
                for (int nf = 0; nf < 4; nf++) {
                    asm volatile(
                        "mma.sync.aligned.m16n8k8.row.col.f32.tf32.tf32.f32 "
                        "{%0,%1,%2,%3}, {%4,%5,%6,%7}, {%8,%9}, {%0,%1,%2,%3};"
                        : "+f"(acc[mf][nf][0]), "+f"(acc[mf][nf][1]),
                          "+f"(acc[mf][nf][2]), "+f"(acc[mf][nf][3])
                        : "r"(ua[cur][mf][0]), "r"(ua[cur][mf][1]),
                          "r"(ua[cur][mf][2]), "r"(ua[cur][mf][3]),
                          "r"(ub[cur][nf][0]), "r"(ub[cur][nf][1]));
                }
        }
    }

    if (mode == 0) {
#pragma unroll
        for (int mf = 0; mf < 4; mf++) {
            const int row0 = m0 + wm * 64 + mf * 16 + r;
#pragma unroll
            for (int nf = 0; nf < 4; nf++) {
                const int col = n0 + wn * 32 + nf * 8 + 2 * c;
                float b0 = 0.f, b1 = 0.f;
                if (bias) { b0 = bias[col]; b1 = bias[col + 1]; }
                float2 v0 = { acc[mf][nf][0] + b0, acc[mf][nf][1] + b1 };
                float2 v1 = { acc[mf][nf][2] + b0, acc[mf][nf][3] + b1 };
                *(float2*)(C + (size_t)row0 * ldc + col) = v0;
                *(float2*)(C + (size_t)(row0 + 8) * ldc + col) = v1;
            }
        }
    } else {
        // transposed epilogue through smem: Ts[n][m], stride 132
        __syncthreads();
        float* Ts = sm;
#pragma unroll
        for (int mf = 0; mf < 4; mf++) {
            const int ml0 = wm * 64 + mf * 16 + r;
#pragma unroll
            for (int nf = 0; nf < 4; nf++) {
                const int nl = wn * 32 + nf * 8 + 2 * c;
                Ts[(nl    ) * 132 + ml0    ] = acc[mf][nf][0];
                Ts[(nl + 1) * 132 + ml0    ] = acc[mf][nf][1];
                Ts[(nl    ) * 132 + ml0 + 8] = acc[mf][nf][2];
                Ts[(nl + 1) * 132 + ml0 + 8] = acc[mf][nf][3];
            }
        }
        __syncthreads();
        const int bbatch = m0 >> 12;
        const int sbase  = m0 & (S_DIM - 1);
#pragma unroll
        for (int it = 0; it < 16; it++) {
            const int idx = tid + it * 256;        // 0..4095
            const int row = idx >> 5;              // n within tile
            const int f   = (idx & 31) * 4;        // m within tile
            float4 v = *(const float4*)(Ts + row * 132 + f);
            const float bv = bias[n0 + row];
            v.x += bv; v.y += bv; v.z += bv; v.w += bv;
            *(float4*)(C + ((size_t)bbatch * D_DIM + n0 + row) * S_DIM + sbase + f) = v;
        }
    }
}

// ---------------------------------------------------------------------------
// Row softmax over S_DIM with folded 1/32 scale: softmax(scale * row).
// ---------------------------------------------------------------------------
__global__ void __launch_bounds__(256) softmax_kernel(float* __restrict__ P, float scale)
{
    float4* row = (float4*)(P + (size_t)blockIdx.x * S_DIM);
    const int tid = threadIdx.x;
    __shared__ float sh[32];

    float4 v[4];
    float mx = -INFINITY;
#pragma unroll
    for (int i = 0; i < 4; i++) {
        v[i] = row[tid + i * 256];
        mx = fmaxf(mx, fmaxf(fmaxf(v[i].x, v[i].y), fmaxf(v[i].z, v[i].w)));
    }
#pragma unroll
    for (int o = 16; o; o >>= 1) mx = fmaxf(mx, __shfl_xor_sync(0xffffffffu, mx, o));
    if ((tid & 31) == 0) sh[tid >> 5] = mx;
    __syncthreads();
    if (tid < 32) {
        float t = (tid < 8) ? sh[tid] : -INFINITY;
#pragma unroll
        for (int o = 4; o; o >>= 1) t = fmaxf(t, __shfl_xor_sync(0xffffffffu, t, o));
        if (tid == 0) sh[0] = t;
    }
    __syncthreads();
    mx = sh[0];
    __syncthreads();

    float sum = 0.f;
#pragma unroll
    for (int i = 0; i < 4; i++) {
        v[i].x = __expf((v[i].x - mx) * scale); sum += v[i].x;
        v[i].y = __expf((v[i].y - mx) * scale); sum += v[i].y;
        v[i].z = __expf((v[i].z - mx) * scale); sum += v[i].z;
        v[i].w = __expf((v[i].w - mx) * scale); sum += v[i].w;
    }
#pragma unroll
    for (int o = 16; o; o >>= 1) sum += __shfl_xor_sync(0xffffffffu, sum, o);
    if ((tid & 31) == 0) sh[tid >> 5] = sum;
    __syncthreads();
    if (tid < 32) {
        float t = (tid < 8) ? sh[tid] : 0.f;
#pragma unroll
        for (int o = 4; o; o >>= 1) t += __shfl_xor_sync(0xffffffffu, t, o);
        if (tid == 0) sh[0] = t;
    }
    __syncthreads();
    const float inv = 1.0f / sh[0];

#pragma unroll
    for (int i = 0; i < 4; i++) {
        v[i].x *= inv; v[i].y *= inv; v[i].z *= inv; v[i].w *= inv;
        row[tid + i * 256] = v[i];
    }
}

// ---------------------------------------------------------------------------
extern "C" void kernel_launch(void* const* d_in, const int* in_sizes, int n_in,
                              void* d_out, int out_size)
{
    (void)in_sizes; (void)n_in; (void)out_size;
    const float* x  = (const float*)d_in[0];
    const float* Wq = (const float*)d_in[1];
    const float* bq = (const float*)d_in[2];
    const float* Wk = (const float*)d_in[3];
    const float* bk = (const float*)d_in[4];
    const float* Wv = (const float*)d_in[5];
    const float* bv = (const float*)d_in[6];
    float* out = (float*)d_out;

    float *Q, *K, *Vt, *S;
    cudaGetSymbolAddress((void**)&Q,  g_Q);
    cudaGetSymbolAddress((void**)&K,  g_K);
    cudaGetSymbolAddress((void**)&Vt, g_Vt);
    cudaGetSymbolAddress((void**)&S,  g_S);

    cudaFuncSetAttribute(gemm_mma, cudaFuncAttributeMaxDynamicSharedMemorySize, SMEM_BYTES);

    const dim3 blk(256);

    // QKV projections (M=16384, N=1024, K=1024)
    const dim3 gProj(D_DIM / BN, M_TOK / BM, 1);
    gemm_mma<<<gProj, blk, SMEM_BYTES>>>(x, Wq, Q,  bq, D_DIM, D_DIM, 0, 0, 0, 0);
    gemm_mma<<<gProj, blk, SMEM_BYTES>>>(x, Wk, K,  bk, D_DIM, D_DIM, 0, 0, 0, 0);
    gemm_mma<<<gProj, blk, SMEM_BYTES>>>(x, Wv, Vt, bv, D_DIM, 0,     0, 0, 0, 1);

    // scores = Q . K^T (1/32 folded into softmax)
    const dim3 gScore(S_DIM / BN, S_DIM / BM, B_DIM);
    gemm_mma<<<gScore, blk, SMEM_BYTES>>>(Q, K, S, nullptr, D_DIM, S_DIM,
                                          (size_t)S_DIM * D_DIM,
                                          (size_t)S_DIM * D_DIM,
                                          (size_t)S_DIM * S_DIM, 0);

    softmax_kernel<<<B_DIM * S_DIM, 256>>>(S, 1.0f / 32.0f);

    // out = P . Vt^T (NT: Vt rows are d, ldb = S_DIM)
    const dim3 gPV(D_DIM / BN, S_DIM / BM, B_DIM);
    gemm_mma<<<gPV, blk, SMEM_BYTES>>>(S, Vt, out, nullptr, S_DIM, D_DIM,
                                       (size_t)S_DIM * S_DIM,
                                       (size_t)D_DIM * S_DIM,
                                       (size_t)S_DIM * D_DIM, 0);
}

// round 10
// speedup vs baseline: 5.0368x; 1.1476x over previous
#include <cuda_runtime.h>
#include <stdint.h>
#include <math.h>

#define B_DIM 4
#define S_DIM 4096
#define D_DIM 1024
#define M_TOK (B_DIM * S_DIM)   // 16384

#define BM 128
#define BN 128
#define BK 32                                // floats; 8 chunks of 16B per row
#define A_TILE_FLOATS (128 * 32)             // 4096
#define STAGE_FLOATS (2 * A_TILE_FLOATS)     // 8192 (A then B)
#define STAGE_BYTES (STAGE_FLOATS * 4)       // 32768
#define STAGES 3
#define SMEM_BYTES (STAGES * STAGE_BYTES)    // 98304

// Scratch (__device__ globals per allocation-free rule)
__device__ float g_X [(size_t)M_TOK * D_DIM];           // 64 MB  (tf32-rounded x)
__device__ float g_W [(size_t)3 * D_DIM * D_DIM];       // 12 MB  (tf32-rounded Wq|Wk|Wv)
__device__ float g_Q [(size_t)M_TOK * D_DIM];           // 64 MB
__device__ float g_K [(size_t)M_TOK * D_DIM];           // 64 MB
__device__ float g_Vt[(size_t)B_DIM * D_DIM * S_DIM];   // 64 MB, [b][d][s]
__device__ float g_S [(size_t)B_DIM * S_DIM * S_DIM];   // 256 MB

__device__ __forceinline__ uint32_t smem_u32(const void* p) {
    uint32_t a;
    asm("{ .reg .u64 t; cvta.to.shared.u64 t, %1; cvt.u32.u64 %0, t; }"
        : "=r"(a) : "l"(p));
    return a;
}

__device__ __forceinline__ float f2tf_f(float f) {
    uint32_t u;
    asm("cvt.rna.tf32.f32 %0, %1;" : "=r"(u) : "f"(f));
    return __uint_as_float(u);
}

__device__ __forceinline__ void cp16(uint32_t dst, const void* src) {
    asm volatile("cp.async.cg.shared.global [%0], [%1], 16;" :: "r"(dst), "l"(src));
}

// ---------------------------------------------------------------------------
// Pre-round fp32 -> tf32-representable fp32 (vectorized, grid-stride)
// ---------------------------------------------------------------------------
__global__ void __launch_bounds__(256) round_tf32_kernel(
    const float4* __restrict__ in, float4* __restrict__ out, int n4)
{
    for (int i = blockIdx.x * 256 + threadIdx.x; i < n4; i += gridDim.x * 256) {
        float4 v = in[i];
        v.x = f2tf_f(v.x); v.y = f2tf_f(v.y);
        v.z = f2tf_f(v.z); v.w = f2tf_f(v.w);
        out[i] = v;
    }
}

// ---------------------------------------------------------------------------
// tf32 mma.sync NT GEMM: C[m,n] = sum_k A[m,k]*B[n,k] (+ bias[n])
// A,B already tf32-rounded fp32, row-major ([M,K] / [N,K]).
// Smem: 128-byte rows (32 floats), 16B chunk ch stored at ch^(row&7).
// mode 0: C row-major [M, ldc].  mode 1: transposed store C[b][n][s] (g_Vt).
// rndC != 0: round outputs to tf32-representable (post-bias).
// ---------------------------------------------------------------------------
__global__ void __launch_bounds__(256, 2) gemm_mma(
    const float* __restrict__ A, const float* __restrict__ B,
    float* __restrict__ C, const float* __restrict__ bias,
    int K, int ldc, size_t sA, size_t sB, size_t sC, int mode, int rndC)
{
    extern __shared__ float sm[];
    const uint32_t smbase = smem_u32(sm);

    A += (size_t)blockIdx.z * sA;
    B += (size_t)blockIdx.z * sB;
    C += (size_t)blockIdx.z * sC;

    const int tid  = threadIdx.x;
    const int wid  = tid >> 5;
    const int lane = tid & 31;
    const int wm = wid >> 2;          // 0..1  (M warp row)
    const int wn = wid & 3;           // 0..3  (N warp col)
    const int r  = lane >> 2;         // 0..7
    const int c  = lane & 3;          // 0..3
    const int m0 = blockIdx.y * BM;
    const int n0 = blockIdx.x * BN;

    // ---- global -> smem mapping (swizzled) ----
    const int lrow = tid >> 1;                 // 0..127
    const int o4   = (tid & 1) * 4;            // starting 16B chunk (0 or 4)
    const int xr   = lrow & 7;
    const float* gA = A + (size_t)(m0 + lrow) * K + o4 * 4;
    const float* gB = B + (size_t)(n0 + lrow) * K + o4 * 4;
    uint32_t dstA[4], dstB[4];
#pragma unroll
    for (int j = 0; j < 4; j++) {
        dstA[j] = (uint32_t)lrow * 128 + (uint32_t)(((o4 + j) ^ xr) << 4);
        dstB[j] = dstA[j] + A_TILE_FLOATS * 4;
    }

    // ---- fragment base offsets (floats, within tile) ----
    int aoff[4], boff[4];
#pragma unroll
    for (int mf = 0; mf < 4; mf++) aoff[mf] = (wm * 64 + mf * 16 + r) * 32;
#pragma unroll
    for (int nf = 0; nf < 4; nf++) boff[nf] = (wn * 32 + nf * 8 + r) * 32;

    const int NC = K / BK;

    float acc[4][4][4];
#pragma unroll
    for (int i = 0; i < 4; i++)
#pragma unroll
        for (int j = 0; j < 4; j++)
#pragma unroll
            for (int v = 0; v < 4; v++) acc[i][j][v] = 0.f;

    auto load_chunk = [&](int ch) {
        if (ch < NC) {
            const uint32_t st = smbase + (uint32_t)(ch % STAGES) * STAGE_BYTES;
            const float* pa = gA + ch * BK;
            const float* pb = gB + ch * BK;
#pragma unroll
            for (int j = 0; j < 4; j++) {
                cp16(st + dstA[j], pa + j * 4);
                cp16(st + dstB[j], pb + j * 4);
            }
        }
        asm volatile("cp.async.commit_group;");
    };

    load_chunk(0);
    load_chunk(1);

    for (int i = 0; i < NC; i++) {
        asm volatile("cp.async.wait_group 1;");
        __syncthreads();
        load_chunk(i + 2);

        const uint32_t* As = (const uint32_t*)(sm + (i % STAGES) * STAGE_FLOATS);
        const uint32_t* Bs = As + A_TILE_FLOATS;

#pragma unroll
        for (int s = 0; s < 4; s++) {
            const int koff = (((2 * s) ^ r) << 2) + c;
            const int koff2 = koff ^ 4;
            uint32_t ua[4][4], ub[4][2];
#pragma unroll
            for (int mf = 0; mf < 4; mf++) {
                ua[mf][0] = As[aoff[mf] + koff];
                ua[mf][1] = As[aoff[mf] + 256 + koff];
                ua[mf][2] = As[aoff[mf] + koff2];
                ua[mf][3] = As[aoff[mf] + 256 + koff2];
            }
#pragma unroll
            for (int nf = 0; nf < 4; nf++) {
                ub[nf][0] = Bs[boff[nf] + koff];
                ub[nf][1] = Bs[boff[nf] + koff2];
            }
#pragma unroll
            for (int mf = 0; mf < 4; mf++)
#pragma unroll
                for (int nf = 0; nf < 4; nf++) {
                    asm volatile(
                        "mma.sync.aligned.m16n8k8.row.col.f32.tf32.tf32.f32 "
                        "{%0,%1,%2,%3}, {%4,%5,%6,%7}, {%8,%9}, {%0,%1,%2,%3};"
                        : "+f"(acc[mf][nf][0]), "+f"(acc[mf][nf][1]),
                          "+f"(acc[mf][nf][2]), "+f"(acc[mf][nf][3])
                        : "r"(ua[mf][0]), "r"(ua[mf][1]),
                          "r"(ua[mf][2]), "r"(ua[mf][3]),
                          "r"(ub[nf][0]), "r"(ub[nf][1]));
                }
        }
    }

    if (mode == 0) {
#pragma unroll
        for (int mf = 0; mf < 4; mf++) {
            const int row0 = m0 + wm * 64 + mf * 16 + r;
#pragma unroll
            for (int nf = 0; nf < 4; nf++) {
                const int col = n0 + wn * 32 + nf * 8 + 2 * c;
                float b0 = 0.f, b1 = 0.f;
                if (bias) { b0 = bias[col]; b1 = bias[col + 1]; }
                float2 v0 = { acc[mf][nf][0] + b0, acc[mf][nf][1] + b1 };
                float2 v1 = { acc[mf][nf][2] + b0, acc[mf][nf][3] + b1 };
                if (rndC) {
                    v0.x = f2tf_f(v0.x); v0.y = f2tf_f(v0.y);
                    v1.x = f2tf_f(v1.x); v1.y = f2tf_f(v1.y);
                }
                *(float2*)(C + (size_t)row0 * ldc + col) = v0;
                *(float2*)(C + (size_t)(row0 + 8) * ldc + col) = v1;
            }
        }
    } else {
        // transposed epilogue through smem: Ts[n][m], stride 132
        __syncthreads();
        float* Ts = sm;
#pragma unroll
        for (int mf = 0; mf < 4; mf++) {
            const int ml0 = wm * 64 + mf * 16 + r;
#pragma unroll
            for (int nf = 0; nf < 4; nf++) {
                const int nl = wn * 32 + nf * 8 + 2 * c;
                Ts[(nl    ) * 132 + ml0    ] = acc[mf][nf][0];
                Ts[(nl + 1) * 132 + ml0    ] = acc[mf][nf][1];
                Ts[(nl    ) * 132 + ml0 + 8] = acc[mf][nf][2];
                Ts[(nl + 1) * 132 + ml0 + 8] = acc[mf][nf][3];
            }
        }
        __syncthreads();
        const int bbatch = m0 >> 12;
        const int sbase  = m0 & (S_DIM - 1);
#pragma unroll
        for (int it = 0; it < 16; it++) {
            const int idx = tid + it * 256;        // 0..4095
            const int row = idx >> 5;              // n within tile
            const int f   = (idx & 31) * 4;        // m within tile
            float4 v = *(const float4*)(Ts + row * 132 + f);
            const float bv = bias[n0 + row];
            v.x = f2tf_f(v.x + bv); v.y = f2tf_f(v.y + bv);
            v.z = f2tf_f(v.z + bv); v.w = f2tf_f(v.w + bv);
            *(float4*)(C + ((size_t)bbatch * D_DIM + n0 + row) * S_DIM + sbase + f) = v;
        }
    }
}

// ---------------------------------------------------------------------------
// Row softmax over S_DIM, folded 1/32 scale; writes tf32-rounded probs.
// ---------------------------------------------------------------------------
__global__ void __launch_bounds__(256) softmax_kernel(float* __restrict__ P, float scale)
{
    float4* row = (float4*)(P + (size_t)blockIdx.x * S_DIM);
    const int tid = threadIdx.x;
    __shared__ float sh[32];

    float4 v[4];
    float mx = -INFINITY;
#pragma unroll
    for (int i = 0; i < 4; i++) {
        v[i] = row[tid + i * 256];
        mx = fmaxf(mx, fmaxf(fmaxf(v[i].x, v[i].y), fmaxf(v[i].z, v[i].w)));
    }
#pragma unroll
    for (int o = 16; o; o >>= 1) mx = fmaxf(mx, __shfl_xor_sync(0xffffffffu, mx, o));
    if ((tid & 31) == 0) sh[tid >> 5] = mx;
    __syncthreads();
    if (tid < 32) {
        float t = (tid < 8) ? sh[tid] : -INFINITY;
#pragma unroll
        for (int o = 4; o; o >>= 1) t = fmaxf(t, __shfl_xor_sync(0xffffffffu, t, o));
        if (tid == 0) sh[0] = t;
    }
    __syncthreads();
    mx = sh[0];
    __syncthreads();

    float sum = 0.f;
#pragma unroll
    for (int i = 0; i < 4; i++) {
        v[i].x = __expf((v[i].x - mx) * scale); sum += v[i].x;
        v[i].y = __expf((v[i].y - mx) * scale); sum += v[i].y;
        v[i].z = __expf((v[i].z - mx) * scale); sum += v[i].z;
        v[i].w = __expf((v[i].w - mx) * scale); sum += v[i].w;
    }
#pragma unroll
    for (int o = 16; o; o >>= 1) sum += __shfl_xor_sync(0xffffffffu, sum, o);
    if ((tid & 31) == 0) sh[tid >> 5] = sum;
    __syncthreads();
    if (tid < 32) {
        float t = (tid < 8) ? sh[tid] : 0.f;
#pragma unroll
        for (int o = 4; o; o >>= 1) t += __shfl_xor_sync(0xffffffffu, t, o);
        if (tid == 0) sh[0] = t;
    }
    __syncthreads();
    const float inv = 1.0f / sh[0];

#pragma unroll
    for (int i = 0; i < 4; i++) {
        v[i].x = f2tf_f(v[i].x * inv); v[i].y = f2tf_f(v[i].y * inv);
        v[i].z = f2tf_f(v[i].z * inv); v[i].w = f2tf_f(v[i].w * inv);
        row[tid + i * 256] = v[i];
    }
}

// ---------------------------------------------------------------------------
extern "C" void kernel_launch(void* const* d_in, const int* in_sizes, int n_in,
                              void* d_out, int out_size)
{
    (void)in_sizes; (void)n_in; (void)out_size;
    const float* x  = (const float*)d_in[0];
    const float* Wq = (const float*)d_in[1];
    const float* bq = (const float*)d_in[2];
    const float* Wk = (const float*)d_in[3];
    const float* bk = (const float*)d_in[4];
    const float* Wv = (const float*)d_in[5];
    const float* bv = (const float*)d_in[6];
    float* out = (float*)d_out;

    float *X, *W, *Q, *K, *Vt, *S;
    cudaGetSymbolAddress((void**)&X,  g_X);
    cudaGetSymbolAddress((void**)&W,  g_W);
    cudaGetSymbolAddress((void**)&Q,  g_Q);
    cudaGetSymbolAddress((void**)&K,  g_K);
    cudaGetSymbolAddress((void**)&Vt, g_Vt);
    cudaGetSymbolAddress((void**)&S,  g_S);

    cudaFuncSetAttribute(gemm_mma, cudaFuncAttributeMaxDynamicSharedMemorySize, SMEM_BYTES);

    // Pre-round inputs to tf32-representable fp32
    round_tf32_kernel<<<1024, 256>>>((const float4*)x,  (float4*)X, (M_TOK * D_DIM) / 4);
    round_tf32_kernel<<<256,  256>>>((const float4*)Wq, (float4*)(W + 0 * D_DIM * D_DIM), (D_DIM * D_DIM) / 4);
    round_tf32_kernel<<<256,  256>>>((const float4*)Wk, (float4*)(W + 1 * D_DIM * D_DIM), (D_DIM * D_DIM) / 4);
    round_tf32_kernel<<<256,  256>>>((const float4*)Wv, (float4*)(W + 2 * D_DIM * D_DIM), (D_DIM * D_DIM) / 4);

    const dim3 blk(256);

    // QKV projections (M=16384, N=1024, K=1024); Q,K rounded; Vt rounded+transposed
    const dim3 gProj(D_DIM / BN, M_TOK / BM, 1);
    gemm_mma<<<gProj, blk, SMEM_BYTES>>>(X, W + 0 * D_DIM * D_DIM, Q,  bq, D_DIM, D_DIM, 0, 0, 0, 0, 1);
    gemm_mma<<<gProj, blk, SMEM_BYTES>>>(X, W + 1 * D_DIM * D_DIM, K,  bk, D_DIM, D_DIM, 0, 0, 0, 0, 1);
    gemm_mma<<<gProj, blk, SMEM_BYTES>>>(X, W + 2 * D_DIM * D_DIM, Vt, bv, D_DIM, 0,     0, 0, 0, 1, 1);

    // scores = Q . K^T (1/32 folded into softmax); raw fp32 scores
    const dim3 gScore(S_DIM / BN, S_DIM / BM, B_DIM);
    gemm_mma<<<gScore, blk, SMEM_BYTES>>>(Q, K, S, nullptr, D_DIM, S_DIM,
                                          (size_t)S_DIM * D_DIM,
                                          (size_t)S_DIM * D_DIM,
                                          (size_t)S_DIM * S_DIM, 0, 0);

    softmax_kernel<<<B_DIM * S_DIM, 256>>>(S, 1.0f / 32.0f);

    // out = P . Vt^T (NT: Vt rows are d, ldb = S_DIM); final fp32 output
    const dim3 gPV(D_DIM / BN, S_DIM / BM, B_DIM);
    gemm_mma<<<gPV, blk, SMEM_BYTES>>>(S, Vt, out, nullptr, S_DIM, D_DIM,
                                       (size_t)S_DIM * S_DIM,
                                       (size_t)D_DIM * S_DIM,
                                       (size_t)S_DIM * D_DIM, 0, 0);
}